// round 14
// baseline (speedup 1.0000x reference)
#include <cuda_runtime.h>
#include <cuda_fp16.h>
#include <cstdint>
#include <cstddef>

// out = x[1024,65536] @ W2[2048,65536]^T, W2[o,l*32+c]=W_pos[o,l]*W_chan[o,c].
// fp16 operands / fp32 accum via mma.sync.m16n8k16. B (=W2) fragments built in
// registers, double-buffered one ks-step ahead. CTA 64x128x128, 8 warps, 2 CTAs/SM.
// Single merged conversion kernel (x and W_pos fp32->fp16, 8 floats/thread).

static constexpr int MB = 1024, NO = 2048, LL = 2048, CC = 32;
static constexpr int KK = LL * CC;                  // 65536

__device__ __half g_xh[(size_t)MB * KK];            // fp16 A
__device__ __half g_wph[(size_t)NO * LL];           // fp16 W_pos (8 MiB)

__device__ __forceinline__ uint32_t pk(float a, float b) {
    __half2 h = __floats2half2_rn(a, b);
    return *reinterpret_cast<uint32_t*>(&h);
}

// x: 64Mi floats -> 8Mi threads -> 32768 blocks; Wp: 4Mi floats -> 2048 blocks.
static constexpr int CVT_XBLK = 32768;
static constexpr int CVT_WBLK = 2048;

__global__ void k_cvt(const float4* __restrict__ x4, const float4* __restrict__ wp4) {
    const int b = blockIdx.x;
    const float4* src;
    uint4* dst;
    int i;
    if (b < CVT_XBLK) {
        i = b * 256 + threadIdx.x;
        src = x4;  dst = reinterpret_cast<uint4*>(g_xh);
    } else {
        i = (b - CVT_XBLK) * 256 + threadIdx.x;
        src = wp4; dst = reinterpret_cast<uint4*>(g_wph);
    }
    float4 v0 = src[2 * i], v1 = src[2 * i + 1];
    uint4 u;
    u.x = pk(v0.x, v0.y); u.y = pk(v0.z, v0.w);
    u.z = pk(v1.x, v1.y); u.w = pk(v1.z, v1.w);
    dst[i] = u;
}

__device__ __forceinline__ uint32_t smem_u32(const void* p) {
    uint32_t a;
    asm("{ .reg .u64 t; cvta.to.shared.u64 t, %1; cvt.u32.u64 %0, t; }" : "=r"(a) : "l"(p));
    return a;
}
__device__ __forceinline__ void cpa16(uint32_t s, const void* g) {
    asm volatile("cp.async.cg.shared.global [%0], [%1], 16;" :: "r"(s), "l"(g) : "memory");
}
__device__ __forceinline__ void cpa8(uint32_t s, const void* g) {
    asm volatile("cp.async.ca.shared.global [%0], [%1], 8;" :: "r"(s), "l"(g) : "memory");
}
#define CP_COMMIT() asm volatile("cp.async.commit_group;" ::: "memory")
#define CP_WAIT(n)  asm volatile("cp.async.wait_group %0;" :: "n"(n) : "memory")

__device__ __forceinline__ void ldsm4(uint32_t* r, uint32_t a) {
    asm volatile("ldmatrix.sync.aligned.m8n8.x4.shared.b16 {%0,%1,%2,%3}, [%4];"
                 : "=r"(r[0]), "=r"(r[1]), "=r"(r[2]), "=r"(r[3]) : "r"(a));
}
__device__ __forceinline__ void mma16816(float* c, const uint32_t* a,
                                         uint32_t b0, uint32_t b1) {
    asm volatile("mma.sync.aligned.m16n8k16.row.col.f32.f16.f16.f32 "
                 "{%0,%1,%2,%3}, {%4,%5,%6,%7}, {%8,%9}, {%0,%1,%2,%3};"
                 : "+f"(c[0]), "+f"(c[1]), "+f"(c[2]), "+f"(c[3])
                 : "r"(a[0]), "r"(a[1]), "r"(a[2]), "r"(a[3]), "r"(b0), "r"(b1));
}
__device__ __forceinline__ uint32_t hmul2(uint32_t a, uint32_t b) {
    uint32_t d;
    asm("mul.rn.f16x2 %0, %1, %2;" : "=r"(d) : "r"(a), "r"(b));
    return d;
}
__device__ __forceinline__ uint32_t prmt1(uint32_t a, uint32_t sel) {
    uint32_t d;
    asm("prmt.b32 %0, %1, %1, %2;" : "=r"(d) : "r"(a), "r"(sel));
    return d;
}

static constexpr int BM = 64, BN = 128, KT = 128;
static constexpr int NIT = KK / KT;                 // 512
// smem layout (bytes)
static constexpr uint32_t WP_OFF = 0;               // Wp slots: 3 x 1KB
static constexpr uint32_t WP_STG = 1024;
static constexpr uint32_t A_OFF  = 3072;            // A slots: 3 x 16KB (64 rows x 256B)
static constexpr uint32_t A_STG  = 16384;
static constexpr uint32_t SMEM_BYTES = A_OFF + 3 * A_STG;   // 52224 -> 2 CTAs/SM

// 16B-chunk swizzle for 256B rows: XOR within each 128B half
__device__ __forceinline__ uint32_t swz(uint32_t chk, uint32_t row) {
    return (chk & 8u) | ((chk & 7u) ^ (row & 7u));
}

__global__ void __launch_bounds__(256, 2) k_gemm(float* __restrict__ out,
                                                 const float* __restrict__ Wc) {
    extern __shared__ char smem[];
    const uint32_t sb = smem_u32(smem);
    const int t = threadIdx.x;
    const int w = t >> 5, l = t & 31;
    const int m0 = blockIdx.y * BM, n0 = blockIdx.x * BN;
    const int wm = (w >> 2) * 32, wn = (w & 3) * 32;   // 2x4 warp grid, warp 32x32

    // per-lane Wc constants: 4 n-groups x 2 k-parities x 2 half2 (verified R8-R13)
    const int c2 = 2 * (l & 3);
    uint32_t wcH[4][2][2];
#pragma unroll
    for (int g = 0; g < 4; ++g) {
        const float* wb = Wc + (size_t)(n0 + wn + g * 8 + (l >> 2)) * CC;
#pragma unroll
        for (int p = 0; p < 2; ++p) {
            const int c = p * 16 + c2;
            wcH[g][p][0] = pk(wb[c], wb[c + 1]);
            wcH[g][p][1] = pk(wb[c + 8], wb[c + 9]);
        }
    }

    // A loader: 64 rows, 4 threads/row, 4 x 16B chunks each (16 chunks per 256B row)
    const int ar = t >> 2, aq = t & 3;
    const __half* gA = g_xh + (size_t)(m0 + ar) * KK;
    const uint32_t arx = (uint32_t)(ar & 7);

    auto load_stage = [&](int it, int slot) {
        const uint32_t ab = sb + A_OFF + (uint32_t)slot * A_STG + (uint32_t)ar * 256u;
        const __half* ga = gA + (size_t)it * KT;
#pragma unroll
        for (int i = 0; i < 4; ++i) {
            const uint32_t c = (uint32_t)(aq + 4 * i);
            cpa16(ab + (swz(c, arx) * 16u), ga + c * 8);
        }
        if (t < 128) {
            cpa8(sb + WP_OFF + (uint32_t)slot * WP_STG + (uint32_t)t * 8u,
                 g_wph + (size_t)(n0 + t) * LL + (size_t)it * 4);
        }
    };

    float acc[2][4][4];
#pragma unroll
    for (int i = 0; i < 2; ++i)
#pragma unroll
        for (int j = 0; j < 4; ++j)
#pragma unroll
            for (int k = 0; k < 4; ++k) acc[i][j][k] = 0.f;

    load_stage(0, 0); CP_COMMIT();
    load_stage(1, 1); CP_COMMIT();

    // ldmatrix lane geometry for A (verified R3-R13)
    const int arow_i = (l & 7) + ((l >> 3) & 1) * 8, achk_i = (l >> 4);
    const uint32_t wp_row0 = (uint32_t)((wn + (l >> 2)) * 8);   // Wp byte offset, g=0

    uint32_t af[2][2][4];
    uint32_t bfrag[2][4][2];
    uint32_t wph2[4];

    int slotC = 0, slotG = 1, slotP = 2;
    for (int it = 0; it < NIT; ++it) {
        CP_WAIT(1);
        __syncthreads();      // slotC's A + Wp published CTA-wide

        if (it + 2 < NIT) { load_stage(it + 2, slotP); CP_COMMIT(); }

        const uint32_t ast = sb + A_OFF + (uint32_t)slotC * A_STG;
        const uint32_t wps = sb + WP_OFF + (uint32_t)slotC * WP_STG;

        uint32_t wpw[4][2];
#pragma unroll
        for (int g = 0; g < 4; ++g) {
            asm volatile("ld.shared.v2.u32 {%0,%1}, [%2];"
                         : "=r"(wpw[g][0]), "=r"(wpw[g][1])
                         : "r"(wps + wp_row0 + (uint32_t)(g * 64)));
        }

        auto load_afrags = [&](int ks, int buf) {
#pragma unroll
            for (int mi = 0; mi < 2; ++mi) {
                const uint32_t row = (uint32_t)(wm + mi * 16 + arow_i);
                const uint32_t chk = (uint32_t)(achk_i + ks * 2);
                ldsm4(af[buf][mi], ast + row * 256u + swz(chk, row) * 16u);
            }
        };

        auto gen_bfrag = [&](int ks, int buf) {
            const int p = ks & 1, lp = ks >> 1;
            const uint32_t sel = (lp & 1) ? 0x3232u : 0x1010u;
#pragma unroll
            for (int g = 0; g < 4; ++g) {
                if (p == 0) wph2[g] = prmt1(wpw[g][lp >> 1], sel);
                bfrag[buf][g][0] = hmul2(wph2[g], wcH[g][p][0]);
                bfrag[buf][g][1] = hmul2(wph2[g], wcH[g][p][1]);
            }
        };

        load_afrags(0, 0);
        gen_bfrag(0, 0);
#pragma unroll
        for (int ks = 0; ks < KT / 16; ++ks) {
            const int bu = ks & 1;
            if (ks + 1 < KT / 16) {
                load_afrags(ks + 1, (ks + 1) & 1);
                gen_bfrag(ks + 1, (ks + 1) & 1);
            }
#pragma unroll
            for (int g = 0; g < 4; ++g) {
                mma16816(acc[0][g], af[bu][0], bfrag[bu][g][0], bfrag[bu][g][1]);
                mma16816(acc[1][g], af[bu][1], bfrag[bu][g][0], bfrag[bu][g][1]);
            }
        }

        const int tmp = slotC;
        slotC = slotG; slotG = slotP; slotP = tmp;
    }

#pragma unroll
    for (int mi = 0; mi < 2; ++mi) {
        const int row = m0 + wm + mi * 16 + (l >> 2);
#pragma unroll
        for (int g = 0; g < 4; ++g) {
            const int col = n0 + wn + g * 8 + (l & 3) * 2;
            float2 lo; lo.x = acc[mi][g][0]; lo.y = acc[mi][g][1];
            float2 hi; hi.x = acc[mi][g][2]; hi.y = acc[mi][g][3];
            *reinterpret_cast<float2*>(out + (size_t)row * NO + col) = lo;
            *reinterpret_cast<float2*>(out + (size_t)(row + 8) * NO + col) = hi;
        }
    }
}

extern "C" void kernel_launch(void* const* d_in, const int* in_sizes, int n_in,
                              void* d_out, int out_size) {
    (void)in_sizes; (void)n_in; (void)out_size;
    const float* x  = (const float*)d_in[0];
    const float* Wp = (const float*)d_in[1];
    const float* Wc = (const float*)d_in[2];
    float* out = (float*)d_out;

    k_cvt<<<CVT_XBLK + CVT_WBLK, 256>>>(reinterpret_cast<const float4*>(x),
                                        reinterpret_cast<const float4*>(Wp));
    cudaFuncSetAttribute(k_gemm, cudaFuncAttributeMaxDynamicSharedMemorySize,
                         (int)SMEM_BYTES);
    dim3 grid(NO / BN, MB / BM);
    k_gemm<<<grid, 256, SMEM_BYTES>>>(out, Wc);
}

// round 15
// speedup vs baseline: 1.6391x; 1.6391x over previous
#include <cuda_runtime.h>
#include <cuda_fp16.h>
#include <cstdint>
#include <cstddef>

// out = x[1024,65536] @ W2[2048,65536]^T, W2[o,l*32+c]=W_pos[o,l]*W_chan[o,c].
// fp16 operands / fp32 accum via mma.sync.m16n8k16; register-resident B gen.
// STREAM-K: 296 CTAs (2/SM exactly), each owns a contiguous ~443-iteration
// slice of the flattened 256-tile x 512-k-iter space; partial-tile results
// combined via atomicAdd into zero-initialized out.

static constexpr int MB = 1024, NO = 2048, LL = 2048, CC = 32;
static constexpr int KK = LL * CC;                  // 65536

__device__ __half g_xh[(size_t)MB * KK];            // fp16 A
__device__ __half g_wph[(size_t)NO * LL];           // fp16 W_pos

__device__ __forceinline__ uint32_t pk(float a, float b) {
    __half2 h = __floats2half2_rn(a, b);
    return *reinterpret_cast<uint32_t*>(&h);
}

__global__ void k_convert(const float4* __restrict__ x4) {
    int i = blockIdx.x * 256 + threadIdx.x;
    float4 v = x4[i];
    uint2 u; u.x = pk(v.x, v.y); u.y = pk(v.z, v.w);
    reinterpret_cast<uint2*>(g_xh)[i] = u;
}

__global__ void k_wph(const float4* __restrict__ wp4) {
    int i = blockIdx.x * 256 + threadIdx.x;
    float4 v = wp4[i];
    uint2 u; u.x = pk(v.x, v.y); u.y = pk(v.z, v.w);
    reinterpret_cast<uint2*>(g_wph)[i] = u;
}

__global__ void k_zero(float4* __restrict__ o4) {
    o4[blockIdx.x * 256 + threadIdx.x] = make_float4(0.f, 0.f, 0.f, 0.f);
}

__device__ __forceinline__ uint32_t smem_u32(const void* p) {
    uint32_t a;
    asm("{ .reg .u64 t; cvta.to.shared.u64 t, %1; cvt.u32.u64 %0, t; }" : "=r"(a) : "l"(p));
    return a;
}
__device__ __forceinline__ void cpa16(uint32_t s, const void* g) {
    asm volatile("cp.async.cg.shared.global [%0], [%1], 16;" :: "r"(s), "l"(g) : "memory");
}
__device__ __forceinline__ void cpa8(uint32_t s, const void* g) {
    asm volatile("cp.async.ca.shared.global [%0], [%1], 8;" :: "r"(s), "l"(g) : "memory");
}
#define CP_COMMIT() asm volatile("cp.async.commit_group;" ::: "memory")
#define CP_WAIT(n)  asm volatile("cp.async.wait_group %0;" :: "n"(n) : "memory")

__device__ __forceinline__ void ldsm4(uint32_t* r, uint32_t a) {
    asm volatile("ldmatrix.sync.aligned.m8n8.x4.shared.b16 {%0,%1,%2,%3}, [%4];"
                 : "=r"(r[0]), "=r"(r[1]), "=r"(r[2]), "=r"(r[3]) : "r"(a));
}
__device__ __forceinline__ void mma16816(float* c, const uint32_t* a,
                                         uint32_t b0, uint32_t b1) {
    asm volatile("mma.sync.aligned.m16n8k16.row.col.f32.f16.f16.f32 "
                 "{%0,%1,%2,%3}, {%4,%5,%6,%7}, {%8,%9}, {%0,%1,%2,%3};"
                 : "+f"(c[0]), "+f"(c[1]), "+f"(c[2]), "+f"(c[3])
                 : "r"(a[0]), "r"(a[1]), "r"(a[2]), "r"(a[3]), "r"(b0), "r"(b1));
}
__device__ __forceinline__ uint32_t hmul2(uint32_t a, uint32_t b) {
    uint32_t d;
    asm("mul.rn.f16x2 %0, %1, %2;" : "=r"(d) : "r"(a), "r"(b));
    return d;
}
__device__ __forceinline__ uint32_t prmt1(uint32_t a, uint32_t sel) {
    uint32_t d;
    asm("prmt.b32 %0, %1, %1, %2;" : "=r"(d) : "r"(a), "r"(sel));
    return d;
}

static constexpr int BM = 64, BN = 128, KT = 128;
static constexpr int NIT = KK / KT;                 // 512 k-iters per tile
static constexpr int NTILE = (MB / BM) * (NO / BN); // 256
static constexpr int NWORK = 296;                   // 148 SMs x 2 CTAs
static constexpr int TOTIT = NTILE * NIT;           // 131072
static constexpr int QBASE = TOTIT / NWORK;         // 442
static constexpr int QREM  = TOTIT % NWORK;         // 240
// smem layout (bytes)
static constexpr uint32_t WP_OFF = 0;               // Wp slots: 3 x 1KB
static constexpr uint32_t WP_STG = 1024;
static constexpr uint32_t A_OFF  = 3072;            // A slots: 3 x 16KB (64 rows x 256B)
static constexpr uint32_t A_STG  = 16384;
static constexpr uint32_t SMEM_BYTES = A_OFF + 3 * A_STG;   // 52224 -> 2 CTAs/SM

// 16B-chunk swizzle for 256B rows: XOR within each 128B half
__device__ __forceinline__ uint32_t swz(uint32_t chk, uint32_t row) {
    return (chk & 8u) | ((chk & 7u) ^ (row & 7u));
}

__global__ void __launch_bounds__(256, 2) k_gemm(float* __restrict__ out,
                                                 const float* __restrict__ Wc) {
    extern __shared__ char smem[];
    const uint32_t sb = smem_u32(smem);
    const int t = threadIdx.x;
    const int w = t >> 5, l = t & 31;
    const int wm = (w >> 2) * 32, wn = (w & 3) * 32;   // 2x4 warp grid, warp 32x32
    const int ar = t >> 2, aq = t & 3;
    const uint32_t arx = (uint32_t)(ar & 7);
    const int arow_i = (l & 7) + ((l >> 3) & 1) * 8, achk_i = (l >> 4);
    const uint32_t wp_row0 = (uint32_t)((wn + (l >> 2)) * 8);
    const int c2 = 2 * (l & 3);

    // this CTA's contiguous iteration range
    const int bid = blockIdx.x;
    int g0 = bid * QBASE + (bid < QREM ? bid : QREM);
    int g1 = g0 + QBASE + (bid < QREM ? 1 : 0);

    while (g0 < g1) {
        const int tile = g0 / NIT;
        const int k0 = g0 - tile * NIT;
        const int kn = min(NIT - k0, g1 - g0);
        g0 += kn;
        const int m0 = (tile >> 4) * BM, n0 = (tile & 15) * BN;

        CP_WAIT(0);
        __syncthreads();      // all threads done with previous segment's smem

        // per-lane Wc constants for this n-tile (verified geometry R8-R13)
        uint32_t wcH[4][2][2];
#pragma unroll
        for (int g = 0; g < 4; ++g) {
            const float* wb = Wc + (size_t)(n0 + wn + g * 8 + (l >> 2)) * CC;
#pragma unroll
            for (int p = 0; p < 2; ++p) {
                const int c = p * 16 + c2;
                wcH[g][p][0] = pk(wb[c], wb[c + 1]);
                wcH[g][p][1] = pk(wb[c + 8], wb[c + 9]);
            }
        }

        const __half* gA = g_xh + (size_t)(m0 + ar) * KK;

        auto load_stage = [&](int j, int slot) {
            const uint32_t ab = sb + A_OFF + (uint32_t)slot * A_STG + (uint32_t)ar * 256u;
            const __half* ga = gA + (size_t)(k0 + j) * KT;
#pragma unroll
            for (int i = 0; i < 4; ++i) {
                const uint32_t c = (uint32_t)(aq + 4 * i);
                cpa16(ab + (swz(c, arx) * 16u), ga + c * 8);
            }
            if (t < 128) {
                cpa8(sb + WP_OFF + (uint32_t)slot * WP_STG + (uint32_t)t * 8u,
                     g_wph + (size_t)(n0 + t) * LL + (size_t)(k0 + j) * 4);
            }
        };

        float acc[2][4][4];
#pragma unroll
        for (int i = 0; i < 2; ++i)
#pragma unroll
            for (int j = 0; j < 4; ++j)
#pragma unroll
                for (int k = 0; k < 4; ++k) acc[i][j][k] = 0.f;

        load_stage(0, 0); CP_COMMIT();
        if (kn > 1) load_stage(1, 1);
        CP_COMMIT();

        uint32_t af[2][2][4];
        uint32_t bfrag[2][4][2];
        uint32_t wph2[4];

        int slotC = 0, slotG = 1, slotP = 2;
        for (int it = 0; it < kn; ++it) {
            if (it + 1 < kn) { CP_WAIT(1); } else { CP_WAIT(0); }
            __syncthreads();

            if (it + 2 < kn) { load_stage(it + 2, slotP); CP_COMMIT(); }

            const uint32_t ast = sb + A_OFF + (uint32_t)slotC * A_STG;
            const uint32_t wps = sb + WP_OFF + (uint32_t)slotC * WP_STG;

            uint32_t wpw[4][2];
#pragma unroll
            for (int g = 0; g < 4; ++g) {
                asm volatile("ld.shared.v2.u32 {%0,%1}, [%2];"
                             : "=r"(wpw[g][0]), "=r"(wpw[g][1])
                             : "r"(wps + wp_row0 + (uint32_t)(g * 64)));
            }

            auto load_afrags = [&](int ks, int buf) {
#pragma unroll
                for (int mi = 0; mi < 2; ++mi) {
                    const uint32_t row = (uint32_t)(wm + mi * 16 + arow_i);
                    const uint32_t chk = (uint32_t)(achk_i + ks * 2);
                    ldsm4(af[buf][mi], ast + row * 256u + swz(chk, row) * 16u);
                }
            };
            auto gen_bfrag = [&](int ks, int buf) {
                const int p = ks & 1, lp = ks >> 1;
                const uint32_t sel = (lp & 1) ? 0x3232u : 0x1010u;
#pragma unroll
                for (int g = 0; g < 4; ++g) {
                    if (p == 0) wph2[g] = prmt1(wpw[g][lp >> 1], sel);
                    bfrag[buf][g][0] = hmul2(wph2[g], wcH[g][p][0]);
                    bfrag[buf][g][1] = hmul2(wph2[g], wcH[g][p][1]);
                }
            };

            load_afrags(0, 0);
            gen_bfrag(0, 0);
#pragma unroll
            for (int ks = 0; ks < KT / 16; ++ks) {
                const int bu = ks & 1;
                if (ks + 1 < KT / 16) {
                    load_afrags(ks + 1, (ks + 1) & 1);
                    gen_bfrag(ks + 1, (ks + 1) & 1);
                }
#pragma unroll
                for (int g = 0; g < 4; ++g) {
                    mma16816(acc[0][g], af[bu][0], bfrag[bu][g][0], bfrag[bu][g][1]);
                    mma16816(acc[1][g], af[bu][1], bfrag[bu][g][0], bfrag[bu][g][1]);
                }
            }

            const int tmp = slotC;
            slotC = slotG; slotG = slotP; slotP = tmp;
        }

        // partial-tile epilogue: commutative atomic accumulation
#pragma unroll
        for (int mi = 0; mi < 2; ++mi) {
            const int row = m0 + wm + mi * 16 + (l >> 2);
#pragma unroll
            for (int g = 0; g < 4; ++g) {
                const int col = n0 + wn + g * 8 + (l & 3) * 2;
                float* p0 = out + (size_t)row * NO + col;
                float* p1 = out + (size_t)(row + 8) * NO + col;
                atomicAdd(p0,     acc[mi][g][0]);
                atomicAdd(p0 + 1, acc[mi][g][1]);
                atomicAdd(p1,     acc[mi][g][2]);
                atomicAdd(p1 + 1, acc[mi][g][3]);
            }
        }
    }
}

extern "C" void kernel_launch(void* const* d_in, const int* in_sizes, int n_in,
                              void* d_out, int out_size) {
    (void)in_sizes; (void)n_in; (void)out_size;
    const float* x  = (const float*)d_in[0];
    const float* Wp = (const float*)d_in[1];
    const float* Wc = (const float*)d_in[2];
    float* out = (float*)d_out;

    k_convert<<<(MB * (KK / 4)) / 256, 256>>>(reinterpret_cast<const float4*>(x));
    k_wph<<<(NO * (LL / 4)) / 256, 256>>>(reinterpret_cast<const float4*>(Wp));
    k_zero<<<(MB * NO / 4) / 256, 256>>>(reinterpret_cast<float4*>(out));
    cudaFuncSetAttribute(k_gemm, cudaFuncAttributeMaxDynamicSharedMemorySize,
                         (int)SMEM_BYTES);
    k_gemm<<<NWORK, 256, SMEM_BYTES>>>(out, Wc);
}

// round 16
// speedup vs baseline: 1.6412x; 1.0013x over previous
#include <cuda_runtime.h>
#include <cuda_fp16.h>
#include <cstdint>
#include <cstddef>

// out = x[1024,65536] @ W2[2048,65536]^T, W2[o,l*32+c]=W_pos[o,l]*W_chan[o,c].
// fp16 operands / fp32 accum via mma.sync.m16n8k16; register-resident B gen.
// STREAM-K: 296 CTAs (2/SM), contiguous slices of the 256x512 iter space,
// atomicAdd partial-tile epilogue. 6-slot cp.async pipeline, ONE sync per
// TWO k-iters, prefetch distance 4, hoisted ldsm address table.

static constexpr int MB = 1024, NO = 2048, LL = 2048, CC = 32;
static constexpr int KK = LL * CC;                  // 65536

__device__ __half g_xh[(size_t)MB * KK];            // fp16 A
__device__ __half g_wph[(size_t)NO * LL];           // fp16 W_pos

__device__ __forceinline__ uint32_t pk(float a, float b) {
    __half2 h = __floats2half2_rn(a, b);
    return *reinterpret_cast<uint32_t*>(&h);
}

__global__ void k_convert(const float4* __restrict__ x4) {
    int i = blockIdx.x * 256 + threadIdx.x;
    float4 v = x4[i];
    uint2 u; u.x = pk(v.x, v.y); u.y = pk(v.z, v.w);
    reinterpret_cast<uint2*>(g_xh)[i] = u;
}

__global__ void k_wph(const float4* __restrict__ wp4) {
    int i = blockIdx.x * 256 + threadIdx.x;
    float4 v = wp4[i];
    uint2 u; u.x = pk(v.x, v.y); u.y = pk(v.z, v.w);
    reinterpret_cast<uint2*>(g_wph)[i] = u;
}

__global__ void k_zero(float4* __restrict__ o4) {
    o4[blockIdx.x * 256 + threadIdx.x] = make_float4(0.f, 0.f, 0.f, 0.f);
}

__device__ __forceinline__ uint32_t smem_u32(const void* p) {
    uint32_t a;
    asm("{ .reg .u64 t; cvta.to.shared.u64 t, %1; cvt.u32.u64 %0, t; }" : "=r"(a) : "l"(p));
    return a;
}
__device__ __forceinline__ void cpa16(uint32_t s, const void* g) {
    asm volatile("cp.async.cg.shared.global [%0], [%1], 16;" :: "r"(s), "l"(g) : "memory");
}
__device__ __forceinline__ void cpa8(uint32_t s, const void* g) {
    asm volatile("cp.async.ca.shared.global [%0], [%1], 8;" :: "r"(s), "l"(g) : "memory");
}
#define CP_COMMIT() asm volatile("cp.async.commit_group;" ::: "memory")
#define CP_WAIT(n)  asm volatile("cp.async.wait_group %0;" :: "n"(n) : "memory")

__device__ __forceinline__ void ldsm4(uint32_t* r, uint32_t a) {
    asm volatile("ldmatrix.sync.aligned.m8n8.x4.shared.b16 {%0,%1,%2,%3}, [%4];"
                 : "=r"(r[0]), "=r"(r[1]), "=r"(r[2]), "=r"(r[3]) : "r"(a));
}
__device__ __forceinline__ void mma16816(float* c, const uint32_t* a,
                                         uint32_t b0, uint32_t b1) {
    asm volatile("mma.sync.aligned.m16n8k16.row.col.f32.f16.f16.f32 "
                 "{%0,%1,%2,%3}, {%4,%5,%6,%7}, {%8,%9}, {%0,%1,%2,%3};"
                 : "+f"(c[0]), "+f"(c[1]), "+f"(c[2]), "+f"(c[3])
                 : "r"(a[0]), "r"(a[1]), "r"(a[2]), "r"(a[3]), "r"(b0), "r"(b1));
}
__device__ __forceinline__ uint32_t hmul2(uint32_t a, uint32_t b) {
    uint32_t d;
    asm("mul.rn.f16x2 %0, %1, %2;" : "=r"(d) : "r"(a), "r"(b));
    return d;
}
__device__ __forceinline__ uint32_t prmt1(uint32_t a, uint32_t sel) {
    uint32_t d;
    asm("prmt.b32 %0, %1, %1, %2;" : "=r"(d) : "r"(a), "r"(sel));
    return d;
}

static constexpr int BM = 64, BN = 128, KT = 128;
static constexpr int NIT = KK / KT;                 // 512 k-iters per tile
static constexpr int NTILE = (MB / BM) * (NO / BN); // 256
static constexpr int NWORK = 296;                   // 148 SMs x 2 CTAs
static constexpr int TOTIT = NTILE * NIT;           // 131072
static constexpr int QBASE = TOTIT / NWORK;         // 442
static constexpr int QREM  = TOTIT % NWORK;         // 240
static constexpr int NSLOT = 6;
// smem layout (bytes)
static constexpr uint32_t WP_OFF = 0;               // Wp slots: 6 x 1KB
static constexpr uint32_t WP_STG = 1024;
static constexpr uint32_t A_OFF  = 6144;            // A slots: 6 x 16KB (64 rows x 256B)
static constexpr uint32_t A_STG  = 16384;
static constexpr uint32_t SMEM_BYTES = A_OFF + NSLOT * A_STG;   // 104448 -> 2 CTAs/SM

// 16B-chunk swizzle for 256B rows: XOR within each 128B half
__device__ __forceinline__ uint32_t swz(uint32_t chk, uint32_t row) {
    return (chk & 8u) | ((chk & 7u) ^ (row & 7u));
}

__global__ void __launch_bounds__(256, 2) k_gemm(float* __restrict__ out,
                                                 const float* __restrict__ Wc) {
    extern __shared__ char smem[];
    const uint32_t sb = smem_u32(smem);
    const int t = threadIdx.x;
    const int w = t >> 5, l = t & 31;
    const int wm = (w >> 2) * 32, wn = (w & 3) * 32;   // 2x4 warp grid, warp 32x32
    const int ar = t >> 2, aq = t & 3;
    const uint32_t arx = (uint32_t)(ar & 7);
    const int arow_i = (l & 7) + ((l >> 3) & 1) * 8, achk_i = (l >> 4);
    const uint32_t wp_row0 = (uint32_t)((wn + (l >> 2)) * 8);
    const int c2 = 2 * (l & 3);

    // hoisted ldsm address table: aoff[ks] for mi=0; mi=1 is +4096 (row+16 keeps row&7)
    uint32_t aoff[8];
    {
        const uint32_t row0 = (uint32_t)(wm + arow_i);
#pragma unroll
        for (int ks = 0; ks < 8; ++ks)
            aoff[ks] = row0 * 256u + swz((uint32_t)(achk_i + ks * 2), row0) * 16u;
    }

    // this CTA's contiguous iteration range
    const int bid = blockIdx.x;
    int g0 = bid * QBASE + (bid < QREM ? bid : QREM);
    int g1 = g0 + QBASE + (bid < QREM ? 1 : 0);

    while (g0 < g1) {
        const int tile = g0 / NIT;
        const int k0 = g0 - tile * NIT;
        const int kn = min(NIT - k0, g1 - g0);
        g0 += kn;
        const int m0 = (tile >> 4) * BM, n0 = (tile & 15) * BN;

        CP_WAIT(0);
        __syncthreads();      // previous segment's smem fully consumed

        // per-lane Wc constants for this n-tile (verified geometry R8-R15)
        uint32_t wcH[4][2][2];
#pragma unroll
        for (int g = 0; g < 4; ++g) {
            const float* wb = Wc + (size_t)(n0 + wn + g * 8 + (l >> 2)) * CC;
#pragma unroll
            for (int p = 0; p < 2; ++p) {
                const int c = p * 16 + c2;
                wcH[g][p][0] = pk(wb[c], wb[c + 1]);
                wcH[g][p][1] = pk(wb[c + 8], wb[c + 9]);
            }
        }

        const __half* gA = g_xh + (size_t)(m0 + ar) * KK;

        auto load_stage = [&](int j, int slot) {
            const uint32_t ab = sb + A_OFF + (uint32_t)slot * A_STG + (uint32_t)ar * 256u;
            const __half* ga = gA + (size_t)(k0 + j) * KT;
#pragma unroll
            for (int i = 0; i < 4; ++i) {
                const uint32_t c = (uint32_t)(aq + 4 * i);
                cpa16(ab + (swz(c, arx) * 16u), ga + c * 8);
            }
            if (t < 128) {
                cpa8(sb + WP_OFF + (uint32_t)slot * WP_STG + (uint32_t)t * 8u,
                     g_wph + (size_t)(n0 + t) * LL + (size_t)(k0 + j) * 4);
            }
        };

        float acc[2][4][4];
#pragma unroll
        for (int i = 0; i < 2; ++i)
#pragma unroll
            for (int j = 0; j < 4; ++j)
#pragma unroll
                for (int k = 0; k < 4; ++k) acc[i][j][k] = 0.f;

        // one k-iteration: slot's A+Wp assumed published
        auto compute_iter = [&](int slot) {
            const uint32_t ast = sb + A_OFF + (uint32_t)slot * A_STG;
            const uint32_t wps = sb + WP_OFF + (uint32_t)slot * WP_STG;

            uint32_t wpw[4][2];
#pragma unroll
            for (int g = 0; g < 4; ++g) {
                asm volatile("ld.shared.v2.u32 {%0,%1}, [%2];"
                             : "=r"(wpw[g][0]), "=r"(wpw[g][1])
                             : "r"(wps + wp_row0 + (uint32_t)(g * 64)));
            }

            uint32_t af[2][2][4];
            uint32_t bfrag[2][4][2];
            uint32_t wph2[4];

            auto load_afrags = [&](int ks, int buf) {
                ldsm4(af[buf][0], ast + aoff[ks]);
                ldsm4(af[buf][1], ast + aoff[ks] + 4096u);
            };
            auto gen_bfrag = [&](int ks, int buf) {
                const int p = ks & 1, lp = ks >> 1;
                const uint32_t sel = (lp & 1) ? 0x3232u : 0x1010u;
#pragma unroll
                for (int g = 0; g < 4; ++g) {
                    if (p == 0) wph2[g] = prmt1(wpw[g][lp >> 1], sel);
                    bfrag[buf][g][0] = hmul2(wph2[g], wcH[g][p][0]);
                    bfrag[buf][g][1] = hmul2(wph2[g], wcH[g][p][1]);
                }
            };

            load_afrags(0, 0);
            gen_bfrag(0, 0);
#pragma unroll
            for (int ks = 0; ks < 8; ++ks) {
                const int bu = ks & 1;
                if (ks + 1 < 8) {
                    load_afrags(ks + 1, (ks + 1) & 1);
                    gen_bfrag(ks + 1, (ks + 1) & 1);
                }
#pragma unroll
                for (int g = 0; g < 4; ++g) {
                    mma16816(acc[0][g], af[bu][0], bfrag[bu][g][0], bfrag[bu][g][1]);
                    mma16816(acc[1][g], af[bu][1], bfrag[bu][g][0], bfrag[bu][g][1]);
                }
            }
        };

        // prologue: iters 0..3 into slots 0..3 (one commit-group per iter)
        const int npro = kn < 4 ? kn : 4;
        for (int j = 0; j < npro; ++j) { load_stage(j, j); CP_COMMIT(); }

        int s0 = 0;
        for (int i0 = 0; i0 < kn; i0 += 2) {
            if (i0 + 4 <= kn) { CP_WAIT(2); } else { CP_WAIT(0); }
            __syncthreads();   // publishes iters i0, i0+1; frees slots s0+4, s0+5

            int s4 = s0 + 4; if (s4 >= NSLOT) s4 -= NSLOT;
            int s5 = s4 + 1; if (s5 >= NSLOT) s5 -= NSLOT;
            if (i0 + 4 < kn) { load_stage(i0 + 4, s4); CP_COMMIT(); }
            if (i0 + 5 < kn) { load_stage(i0 + 5, s5); CP_COMMIT(); }

            compute_iter(s0);
            int s1 = s0 + 1; if (s1 >= NSLOT) s1 -= NSLOT;
            if (i0 + 1 < kn) compute_iter(s1);

            s0 += 2; if (s0 >= NSLOT) s0 -= NSLOT;
        }

        // partial-tile epilogue: commutative atomic accumulation
#pragma unroll
        for (int mi = 0; mi < 2; ++mi) {
            const int row = m0 + wm + mi * 16 + (l >> 2);
#pragma unroll
            for (int g = 0; g < 4; ++g) {
                const int col = n0 + wn + g * 8 + (l & 3) * 2;
                float* p0 = out + (size_t)row * NO + col;
                float* p1 = out + (size_t)(row + 8) * NO + col;
                atomicAdd(p0,     acc[mi][g][0]);
                atomicAdd(p0 + 1, acc[mi][g][1]);
                atomicAdd(p1,     acc[mi][g][2]);
                atomicAdd(p1 + 1, acc[mi][g][3]);
            }
        }
    }
}

extern "C" void kernel_launch(void* const* d_in, const int* in_sizes, int n_in,
                              void* d_out, int out_size) {
    (void)in_sizes; (void)n_in; (void)out_size;
    const float* x  = (const float*)d_in[0];
    const float* Wp = (const float*)d_in[1];
    const float* Wc = (const float*)d_in[2];
    float* out = (float*)d_out;

    k_convert<<<(MB * (KK / 4)) / 256, 256>>>(reinterpret_cast<const float4*>(x));
    k_wph<<<(NO * (LL / 4)) / 256, 256>>>(reinterpret_cast<const float4*>(Wp));
    k_zero<<<(MB * NO / 4) / 256, 256>>>(reinterpret_cast<float4*>(out));
    cudaFuncSetAttribute(k_gemm, cudaFuncAttributeMaxDynamicSharedMemorySize,
                         (int)SMEM_BYTES);
    k_gemm<<<NWORK, 256, SMEM_BYTES>>>(out, Wc);
}

// round 17
// speedup vs baseline: 1.6677x; 1.0161x over previous
#include <cuda_runtime.h>
#include <cuda_fp16.h>
#include <cstdint>
#include <cstddef>

// out = x[1024,65536] @ W2[2048,65536]^T, W2[o,l*32+c]=W_pos[o,l]*W_chan[o,c].
// fp16 operands / fp32 accum via mma.sync.m16n8k16; register-resident B gen.
// STREAM-K: 296 CTAs (2/SM), contiguous slices of the 256x512 iter space,
// float2-atomicAdd partial-tile epilogue. 6-slot cp.async pipeline, one sync
// per two k-iters. Widened converts; W_pos-convert and out-zero merged.

static constexpr int MB = 1024, NO = 2048, LL = 2048, CC = 32;
static constexpr int KK = LL * CC;                  // 65536

__device__ __half g_xh[(size_t)MB * KK];            // fp16 A
__device__ __half g_wph[(size_t)NO * LL];           // fp16 W_pos

__device__ __forceinline__ uint32_t pk(float a, float b) {
    __half2 h = __floats2half2_rn(a, b);
    return *reinterpret_cast<uint32_t*>(&h);
}

// x convert: 64Mi floats, 8 floats/thread -> 32768 blocks of 256
__global__ void k_convert(const float4* __restrict__ x4) {
    int i = blockIdx.x * 256 + threadIdx.x;
    float4 v0 = x4[2 * i], v1 = x4[2 * i + 1];
    uint4 u;
    u.x = pk(v0.x, v0.y); u.y = pk(v0.z, v0.w);
    u.z = pk(v1.x, v1.y); u.w = pk(v1.z, v1.w);
    reinterpret_cast<uint4*>(g_xh)[i] = u;
}

// blocks [0,2048): W_pos fp32->fp16 (8 floats/thread); [2048,4096): zero out
__global__ void k_wpz(const float4* __restrict__ wp4, float4* __restrict__ o4) {
    const int b = blockIdx.x;
    if (b < 2048) {
        int i = b * 256 + threadIdx.x;
        float4 v0 = wp4[2 * i], v1 = wp4[2 * i + 1];
        uint4 u;
        u.x = pk(v0.x, v0.y); u.y = pk(v0.z, v0.w);
        u.z = pk(v1.x, v1.y); u.w = pk(v1.z, v1.w);
        reinterpret_cast<uint4*>(g_wph)[i] = u;
    } else {
        o4[(b - 2048) * 256 + threadIdx.x] = make_float4(0.f, 0.f, 0.f, 0.f);
    }
}

__device__ __forceinline__ uint32_t smem_u32(const void* p) {
    uint32_t a;
    asm("{ .reg .u64 t; cvta.to.shared.u64 t, %1; cvt.u32.u64 %0, t; }" : "=r"(a) : "l"(p));
    return a;
}
__device__ __forceinline__ void cpa16(uint32_t s, const void* g) {
    asm volatile("cp.async.cg.shared.global [%0], [%1], 16;" :: "r"(s), "l"(g) : "memory");
}
__device__ __forceinline__ void cpa8(uint32_t s, const void* g) {
    asm volatile("cp.async.ca.shared.global [%0], [%1], 8;" :: "r"(s), "l"(g) : "memory");
}
#define CP_COMMIT() asm volatile("cp.async.commit_group;" ::: "memory")
#define CP_WAIT(n)  asm volatile("cp.async.wait_group %0;" :: "n"(n) : "memory")

__device__ __forceinline__ void ldsm4(uint32_t* r, uint32_t a) {
    asm volatile("ldmatrix.sync.aligned.m8n8.x4.shared.b16 {%0,%1,%2,%3}, [%4];"
                 : "=r"(r[0]), "=r"(r[1]), "=r"(r[2]), "=r"(r[3]) : "r"(a));
}
__device__ __forceinline__ void mma16816(float* c, const uint32_t* a,
                                         uint32_t b0, uint32_t b1) {
    asm volatile("mma.sync.aligned.m16n8k16.row.col.f32.f16.f16.f32 "
                 "{%0,%1,%2,%3}, {%4,%5,%6,%7}, {%8,%9}, {%0,%1,%2,%3};"
                 : "+f"(c[0]), "+f"(c[1]), "+f"(c[2]), "+f"(c[3])
                 : "r"(a[0]), "r"(a[1]), "r"(a[2]), "r"(a[3]), "r"(b0), "r"(b1));
}
__device__ __forceinline__ uint32_t hmul2(uint32_t a, uint32_t b) {
    uint32_t d;
    asm("mul.rn.f16x2 %0, %1, %2;" : "=r"(d) : "r"(a), "r"(b));
    return d;
}
__device__ __forceinline__ uint32_t prmt1(uint32_t a, uint32_t sel) {
    uint32_t d;
    asm("prmt.b32 %0, %1, %1, %2;" : "=r"(d) : "r"(a), "r"(sel));
    return d;
}

static constexpr int BM = 64, BN = 128, KT = 128;
static constexpr int NIT = KK / KT;                 // 512 k-iters per tile
static constexpr int NTILE = (MB / BM) * (NO / BN); // 256
static constexpr int NWORK = 296;                   // 148 SMs x 2 CTAs
static constexpr int TOTIT = NTILE * NIT;           // 131072
static constexpr int QBASE = TOTIT / NWORK;         // 442
static constexpr int QREM  = TOTIT % NWORK;         // 240
static constexpr int NSLOT = 6;
// smem layout (bytes)
static constexpr uint32_t WP_OFF = 0;               // Wp slots: 6 x 1KB
static constexpr uint32_t WP_STG = 1024;
static constexpr uint32_t A_OFF  = 6144;            // A slots: 6 x 16KB (64 rows x 256B)
static constexpr uint32_t A_STG  = 16384;
static constexpr uint32_t SMEM_BYTES = A_OFF + NSLOT * A_STG;   // 104448 -> 2 CTAs/SM

// 16B-chunk swizzle for 256B rows: XOR within each 128B half
__device__ __forceinline__ uint32_t swz(uint32_t chk, uint32_t row) {
    return (chk & 8u) | ((chk & 7u) ^ (row & 7u));
}

__global__ void __launch_bounds__(256, 2) k_gemm(float* __restrict__ out,
                                                 const float* __restrict__ Wc) {
    extern __shared__ char smem[];
    const uint32_t sb = smem_u32(smem);
    const int t = threadIdx.x;
    const int w = t >> 5, l = t & 31;
    const int wm = (w >> 2) * 32, wn = (w & 3) * 32;   // 2x4 warp grid, warp 32x32
    const int ar = t >> 2, aq = t & 3;
    const uint32_t arx = (uint32_t)(ar & 7);
    const int arow_i = (l & 7) + ((l >> 3) & 1) * 8, achk_i = (l >> 4);
    const uint32_t wp_row0 = (uint32_t)((wn + (l >> 2)) * 8);
    const int c2 = 2 * (l & 3);

    // hoisted ldsm address table: aoff[ks] for mi=0; mi=1 is +4096
    uint32_t aoff[8];
    {
        const uint32_t row0 = (uint32_t)(wm + arow_i);
#pragma unroll
        for (int ks = 0; ks < 8; ++ks)
            aoff[ks] = row0 * 256u + swz((uint32_t)(achk_i + ks * 2), row0) * 16u;
    }

    const int bid = blockIdx.x;
    int g0 = bid * QBASE + (bid < QREM ? bid : QREM);
    int g1 = g0 + QBASE + (bid < QREM ? 1 : 0);

    while (g0 < g1) {
        const int tile = g0 / NIT;
        const int k0 = g0 - tile * NIT;
        const int kn = min(NIT - k0, g1 - g0);
        g0 += kn;
        const int m0 = (tile >> 4) * BM, n0 = (tile & 15) * BN;

        CP_WAIT(0);
        __syncthreads();      // previous segment's smem fully consumed

        uint32_t wcH[4][2][2];
#pragma unroll
        for (int g = 0; g < 4; ++g) {
            const float* wb = Wc + (size_t)(n0 + wn + g * 8 + (l >> 2)) * CC;
#pragma unroll
            for (int p = 0; p < 2; ++p) {
                const int c = p * 16 + c2;
                wcH[g][p][0] = pk(wb[c], wb[c + 1]);
                wcH[g][p][1] = pk(wb[c + 8], wb[c + 9]);
            }
        }

        const __half* gA = g_xh + (size_t)(m0 + ar) * KK;

        auto load_stage = [&](int j, int slot) {
            const uint32_t ab = sb + A_OFF + (uint32_t)slot * A_STG + (uint32_t)ar * 256u;
            const __half* ga = gA + (size_t)(k0 + j) * KT;
#pragma unroll
            for (int i = 0; i < 4; ++i) {
                const uint32_t c = (uint32_t)(aq + 4 * i);
                cpa16(ab + (swz(c, arx) * 16u), ga + c * 8);
            }
            if (t < 128) {
                cpa8(sb + WP_OFF + (uint32_t)slot * WP_STG + (uint32_t)t * 8u,
                     g_wph + (size_t)(n0 + t) * LL + (size_t)(k0 + j) * 4);
            }
        };

        float acc[2][4][4];
#pragma unroll
        for (int i = 0; i < 2; ++i)
#pragma unroll
            for (int j = 0; j < 4; ++j)
#pragma unroll
                for (int k = 0; k < 4; ++k) acc[i][j][k] = 0.f;

        auto compute_iter = [&](int slot) {
            const uint32_t ast = sb + A_OFF + (uint32_t)slot * A_STG;
            const uint32_t wps = sb + WP_OFF + (uint32_t)slot * WP_STG;

            uint32_t wpw[4][2];
#pragma unroll
            for (int g = 0; g < 4; ++g) {
                asm volatile("ld.shared.v2.u32 {%0,%1}, [%2];"
                             : "=r"(wpw[g][0]), "=r"(wpw[g][1])
                             : "r"(wps + wp_row0 + (uint32_t)(g * 64)));
            }

            uint32_t af[2][2][4];
            uint32_t bfrag[2][4][2];
            uint32_t wph2[4];

            auto load_afrags = [&](int ks, int buf) {
                ldsm4(af[buf][0], ast + aoff[ks]);
                ldsm4(af[buf][1], ast + aoff[ks] + 4096u);
            };
            auto gen_bfrag = [&](int ks, int buf) {
                const int p = ks & 1, lp = ks >> 1;
                const uint32_t sel = (lp & 1) ? 0x3232u : 0x1010u;
#pragma unroll
                for (int g = 0; g < 4; ++g) {
                    if (p == 0) wph2[g] = prmt1(wpw[g][lp >> 1], sel);
                    bfrag[buf][g][0] = hmul2(wph2[g], wcH[g][p][0]);
                    bfrag[buf][g][1] = hmul2(wph2[g], wcH[g][p][1]);
                }
            };

            load_afrags(0, 0);
            gen_bfrag(0, 0);
#pragma unroll
            for (int ks = 0; ks < 8; ++ks) {
                const int bu = ks & 1;
                if (ks + 1 < 8) {
                    load_afrags(ks + 1, (ks + 1) & 1);
                    gen_bfrag(ks + 1, (ks + 1) & 1);
                }
#pragma unroll
                for (int g = 0; g < 4; ++g) {
                    mma16816(acc[0][g], af[bu][0], bfrag[bu][g][0], bfrag[bu][g][1]);
                    mma16816(acc[1][g], af[bu][1], bfrag[bu][g][0], bfrag[bu][g][1]);
                }
            }
        };

        const int npro = kn < 4 ? kn : 4;
        for (int j = 0; j < npro; ++j) { load_stage(j, j); CP_COMMIT(); }

        int s0 = 0;
        for (int i0 = 0; i0 < kn; i0 += 2) {
            if (i0 + 4 <= kn) { CP_WAIT(2); } else { CP_WAIT(0); }
            __syncthreads();   // publishes iters i0, i0+1; frees slots s0+4, s0+5

            int s4 = s0 + 4; if (s4 >= NSLOT) s4 -= NSLOT;
            int s5 = s4 + 1; if (s5 >= NSLOT) s5 -= NSLOT;
            if (i0 + 4 < kn) { load_stage(i0 + 4, s4); CP_COMMIT(); }
            if (i0 + 5 < kn) { load_stage(i0 + 5, s5); CP_COMMIT(); }

            compute_iter(s0);
            int s1 = s0 + 1; if (s1 >= NSLOT) s1 -= NSLOT;
            if (i0 + 1 < kn) compute_iter(s1);

            s0 += 2; if (s0 >= NSLOT) s0 -= NSLOT;
        }

        // partial-tile epilogue: float2 atomic accumulation (8B-aligned cols)
#pragma unroll
        for (int mi = 0; mi < 2; ++mi) {
            const int row = m0 + wm + mi * 16 + (l >> 2);
#pragma unroll
            for (int g = 0; g < 4; ++g) {
                const int col = n0 + wn + g * 8 + (l & 3) * 2;
                float2* p0 = reinterpret_cast<float2*>(out + (size_t)row * NO + col);
                float2* p1 = reinterpret_cast<float2*>(out + (size_t)(row + 8) * NO + col);
                atomicAdd(p0, make_float2(acc[mi][g][0], acc[mi][g][1]));
                atomicAdd(p1, make_float2(acc[mi][g][2], acc[mi][g][3]));
            }
        }
    }
}

extern "C" void kernel_launch(void* const* d_in, const int* in_sizes, int n_in,
                              void* d_out, int out_size) {
    (void)in_sizes; (void)n_in; (void)out_size;
    const float* x  = (const float*)d_in[0];
    const float* Wp = (const float*)d_in[1];
    const float* Wc = (const float*)d_in[2];
    float* out = (float*)d_out;

    k_convert<<<(MB * (KK / 8)) / 256, 256>>>(reinterpret_cast<const float4*>(x));
    k_wpz<<<4096, 256>>>(reinterpret_cast<const float4*>(Wp),
                         reinterpret_cast<float4*>(out));
    cudaFuncSetAttribute(k_gemm, cudaFuncAttributeMaxDynamicSharedMemorySize,
                         (int)SMEM_BYTES);
    k_gemm<<<NWORK, 256, SMEM_BYTES>>>(out, Wc);
}